// round 4
// baseline (speedup 1.0000x reference)
#include <cuda_runtime.h>
#include <math.h>

#define N_NODES 50000
#define N_EDGES 1600000
#define NFEAT 256
#define NHID 64
#define NCLASS 16

// ---------------------------------------------------------------------------
// Static scratch (~42 MB) — no cudaMalloc allowed anywhere.
// ---------------------------------------------------------------------------
__device__ float g_sup1[N_NODES * NHID];    // x @ W1
__device__ float g_h[N_NODES * NHID];       // spmm1 result + b1
__device__ float g_sup2[N_NODES * NCLASS];  // relu(h) @ W2
__device__ int   g_deg[N_NODES];            // per-dst edge counts
__device__ int   g_rowptr[N_NODES];         // CSR row starts (pristine)
__device__ int   g_pos[N_NODES];            // CSR fill cursors (mutated)
__device__ int   g_esrc[N_EDGES];           // permuted src indices
__device__ float g_ew[N_EDGES];             // permuted edge weights

// ---------------------------------------------------------------------------
// 0) zero the histogram
// ---------------------------------------------------------------------------
__global__ void zero_deg_kernel() {
    int i = blockIdx.x * blockDim.x + threadIdx.x;
    if (i < N_NODES) g_deg[i] = 0;
}

// ---------------------------------------------------------------------------
// 1) histogram of dst (int atomics, well-spread addresses)
// ---------------------------------------------------------------------------
__global__ void hist_kernel(const int* __restrict__ dst) {
    int e = blockIdx.x * blockDim.x + threadIdx.x;
    if (e < N_EDGES) atomicAdd(&g_deg[dst[e]], 1);
}

// ---------------------------------------------------------------------------
// 2) exclusive scan over g_deg -> g_rowptr, g_pos
//    single block, 1024 threads, shfl warp scan (3 barriers per 1024-tile)
// ---------------------------------------------------------------------------
__global__ void __launch_bounds__(1024)
scan_kernel() {
    __shared__ int warpsum[32];
    __shared__ int warpoff[32];
    __shared__ int carry_s;
    int tid  = threadIdx.x;
    int lane = tid & 31;
    int wrp  = tid >> 5;
    if (tid == 0) carry_s = 0;
    __syncthreads();

    for (int base = 0; base < N_NODES; base += 1024) {
        int i = base + tid;
        int v = (i < N_NODES) ? g_deg[i] : 0;

        // inclusive warp scan via shuffles (no barriers)
        int incl = v;
#pragma unroll
        for (int off = 1; off < 32; off <<= 1) {
            int t = __shfl_up_sync(0xffffffffu, incl, off);
            if (lane >= off) incl += t;
        }
        if (lane == 31) warpsum[wrp] = incl;
        __syncthreads();

        // warp 0 scans the 32 warp totals -> exclusive offsets
        if (wrp == 0) {
            int s = warpsum[lane];
            int si = s;
#pragma unroll
            for (int off = 1; off < 32; off <<= 1) {
                int t = __shfl_up_sync(0xffffffffu, si, off);
                if (lane >= off) si += t;
            }
            warpoff[lane] = si - s;   // exclusive prefix of warp sums
        }
        __syncthreads();

        if (i < N_NODES) {
            int r = carry_s + warpoff[wrp] + incl - v;  // exclusive global
            g_rowptr[i] = r;
            g_pos[i]    = r;
        }
        __syncthreads();              // everyone has read carry_s
        if (tid == 0) carry_s += warpoff[31] + warpsum[31];
        __syncthreads();
    }
}

// ---------------------------------------------------------------------------
// 3) scatter edges into CSR order (int atomics only)
// ---------------------------------------------------------------------------
__global__ void scatter_kernel(const int* __restrict__ src,
                               const int* __restrict__ dst,
                               const float* __restrict__ w) {
    int e = blockIdx.x * blockDim.x + threadIdx.x;
    if (e >= N_EDGES) return;
    int d = dst[e];
    int p = atomicAdd(&g_pos[d], 1);
    g_esrc[p] = src[e];
    g_ew[p]   = w[e];
}

// ---------------------------------------------------------------------------
// GEMM1: sup1[50000,64] = x[50000,256] @ W1[256,64]
// 64x64 tile per block, 256 threads, 4x4 register blocking, BK=16.
// ---------------------------------------------------------------------------
__global__ void __launch_bounds__(256)
gemm1_kernel(const float* __restrict__ x, const float* __restrict__ W1) {
    __shared__ float xs[16][68];  // [kk][row], padded
    __shared__ float ws[16][64];  // [kk][col]

    int tid = threadIdx.x;
    int tx = tid & 15;
    int ty = tid >> 4;
    int rowBase = blockIdx.x * 64;

    float acc[4][4];
#pragma unroll
    for (int i = 0; i < 4; i++)
#pragma unroll
        for (int j = 0; j < 4; j++) acc[i][j] = 0.f;

    for (int k0 = 0; k0 < NFEAT; k0 += 16) {
        {
            int r = tid >> 2;
            int kq = (tid & 3) * 4;
            int grow = rowBase + r;
            float4 v = make_float4(0.f, 0.f, 0.f, 0.f);
            if (grow < N_NODES)
                v = *(const float4*)(x + (size_t)grow * NFEAT + k0 + kq);
            xs[kq + 0][r] = v.x;
            xs[kq + 1][r] = v.y;
            xs[kq + 2][r] = v.z;
            xs[kq + 3][r] = v.w;
        }
        {
            int kk = tid >> 4;
            int n = (tid & 15) * 4;
            float4 v = *(const float4*)(W1 + (size_t)(k0 + kk) * NHID + n);
            *(float4*)&ws[kk][n] = v;
        }
        __syncthreads();

#pragma unroll
        for (int kk = 0; kk < 16; kk++) {
            float a0 = xs[kk][ty * 4 + 0];
            float a1 = xs[kk][ty * 4 + 1];
            float a2 = xs[kk][ty * 4 + 2];
            float a3 = xs[kk][ty * 4 + 3];
            float4 bv = *(float4*)&ws[kk][tx * 4];
            acc[0][0] += a0 * bv.x; acc[0][1] += a0 * bv.y; acc[0][2] += a0 * bv.z; acc[0][3] += a0 * bv.w;
            acc[1][0] += a1 * bv.x; acc[1][1] += a1 * bv.y; acc[1][2] += a1 * bv.z; acc[1][3] += a1 * bv.w;
            acc[2][0] += a2 * bv.x; acc[2][1] += a2 * bv.y; acc[2][2] += a2 * bv.z; acc[2][3] += a2 * bv.w;
            acc[3][0] += a3 * bv.x; acc[3][1] += a3 * bv.y; acc[3][2] += a3 * bv.z; acc[3][3] += a3 * bv.w;
        }
        __syncthreads();
    }

#pragma unroll
    for (int i = 0; i < 4; i++) {
        int grow = rowBase + ty * 4 + i;
        if (grow < N_NODES) {
            float4 v = make_float4(acc[i][0], acc[i][1], acc[i][2], acc[i][3]);
            *(float4*)(g_sup1 + (size_t)grow * NHID + tx * 4) = v;
        }
    }
}

// ---------------------------------------------------------------------------
// 4) SpMM1 gather: h[row] = b1 + sum_e w_e * sup1[src_e]
//    16 threads per row, each owns a float4. 4-way unrolled for MLP.
// ---------------------------------------------------------------------------
__global__ void __launch_bounds__(256)
spmm1_csr_kernel(const float* __restrict__ b1) {
    long long t = (long long)blockIdx.x * blockDim.x + threadIdx.x;
    int row = (int)(t >> 4);
    int sub = (int)(t & 15);
    if (row >= N_NODES) return;

    int start = g_rowptr[row];
    int end   = start + g_deg[row];

    float4 acc = make_float4(0.f, 0.f, 0.f, 0.f);
    int e = start;
    // 4-way unroll: issue all four gathers before consuming any
    for (; e + 4 <= end; e += 4) {
        int   s0 = __ldg(&g_esrc[e + 0]);
        int   s1 = __ldg(&g_esrc[e + 1]);
        int   s2 = __ldg(&g_esrc[e + 2]);
        int   s3 = __ldg(&g_esrc[e + 3]);
        float w0 = __ldg(&g_ew[e + 0]);
        float w1 = __ldg(&g_ew[e + 1]);
        float w2 = __ldg(&g_ew[e + 2]);
        float w3 = __ldg(&g_ew[e + 3]);
        float4 v0 = *(const float4*)(g_sup1 + (size_t)s0 * NHID + sub * 4);
        float4 v1 = *(const float4*)(g_sup1 + (size_t)s1 * NHID + sub * 4);
        float4 v2 = *(const float4*)(g_sup1 + (size_t)s2 * NHID + sub * 4);
        float4 v3 = *(const float4*)(g_sup1 + (size_t)s3 * NHID + sub * 4);
        acc.x += w0 * v0.x; acc.y += w0 * v0.y; acc.z += w0 * v0.z; acc.w += w0 * v0.w;
        acc.x += w1 * v1.x; acc.y += w1 * v1.y; acc.z += w1 * v1.z; acc.w += w1 * v1.w;
        acc.x += w2 * v2.x; acc.y += w2 * v2.y; acc.z += w2 * v2.z; acc.w += w2 * v2.w;
        acc.x += w3 * v3.x; acc.y += w3 * v3.y; acc.z += w3 * v3.z; acc.w += w3 * v3.w;
    }
    for (; e < end; e++) {
        int   s  = __ldg(&g_esrc[e]);
        float wt = __ldg(&g_ew[e]);
        float4 v = *(const float4*)(g_sup1 + (size_t)s * NHID + sub * 4);
        acc.x += wt * v.x; acc.y += wt * v.y; acc.z += wt * v.z; acc.w += wt * v.w;
    }
    float4 bv = *(const float4*)(b1 + sub * 4);
    acc.x += bv.x; acc.y += bv.y; acc.z += bv.z; acc.w += bv.w;
    *(float4*)(g_h + (size_t)row * NHID + sub * 4) = acc;
}

// ---------------------------------------------------------------------------
// GEMM2: sup2[50000,16] = relu(h)[50000,64] @ W2[64,16]; one thread per row
// ---------------------------------------------------------------------------
__global__ void __launch_bounds__(256)
gemm2_kernel(const float* __restrict__ W2) {
    __shared__ float w2s[NHID * NCLASS];
    for (int i = threadIdx.x; i < NHID * NCLASS; i += blockDim.x)
        w2s[i] = W2[i];
    __syncthreads();

    int n = blockIdx.x * blockDim.x + threadIdx.x;
    if (n >= N_NODES) return;

    float acc[NCLASS];
#pragma unroll
    for (int c = 0; c < NCLASS; c++) acc[c] = 0.f;

    const float4* hrow = (const float4*)(g_h + (size_t)n * NHID);
#pragma unroll
    for (int k4 = 0; k4 < NHID / 4; k4++) {
        float4 hv = hrow[k4];
        hv.x = fmaxf(hv.x, 0.f);
        hv.y = fmaxf(hv.y, 0.f);
        hv.z = fmaxf(hv.z, 0.f);
        hv.w = fmaxf(hv.w, 0.f);
        int k = k4 * 4;
#pragma unroll
        for (int c = 0; c < NCLASS; c++) {
            acc[c] += hv.x * w2s[(k + 0) * NCLASS + c];
            acc[c] += hv.y * w2s[(k + 1) * NCLASS + c];
            acc[c] += hv.z * w2s[(k + 2) * NCLASS + c];
            acc[c] += hv.w * w2s[(k + 3) * NCLASS + c];
        }
    }
    float4* o = (float4*)(g_sup2 + (size_t)n * NCLASS);
#pragma unroll
    for (int q = 0; q < 4; q++)
        o[q] = make_float4(acc[q * 4 + 0], acc[q * 4 + 1],
                           acc[q * 4 + 2], acc[q * 4 + 3]);
}

// ---------------------------------------------------------------------------
// 5) SpMM2 gather + bias + log_softmax, fused.
//    4 threads per row, each owns a float4; shuffle reduction. 4-way unroll.
// ---------------------------------------------------------------------------
__global__ void __launch_bounds__(256)
spmm2_csr_kernel(const float* __restrict__ b2, float* __restrict__ out) {
    long long t = (long long)blockIdx.x * blockDim.x + threadIdx.x;
    int row = (int)(t >> 2);
    int sub = (int)(t & 3);
    if (row >= N_NODES) return;

    int start = g_rowptr[row];
    int end   = start + g_deg[row];

    float4 acc = make_float4(0.f, 0.f, 0.f, 0.f);
    int e = start;
    for (; e + 4 <= end; e += 4) {
        int   s0 = __ldg(&g_esrc[e + 0]);
        int   s1 = __ldg(&g_esrc[e + 1]);
        int   s2 = __ldg(&g_esrc[e + 2]);
        int   s3 = __ldg(&g_esrc[e + 3]);
        float w0 = __ldg(&g_ew[e + 0]);
        float w1 = __ldg(&g_ew[e + 1]);
        float w2 = __ldg(&g_ew[e + 2]);
        float w3 = __ldg(&g_ew[e + 3]);
        float4 v0 = *(const float4*)(g_sup2 + (size_t)s0 * NCLASS + sub * 4);
        float4 v1 = *(const float4*)(g_sup2 + (size_t)s1 * NCLASS + sub * 4);
        float4 v2 = *(const float4*)(g_sup2 + (size_t)s2 * NCLASS + sub * 4);
        float4 v3 = *(const float4*)(g_sup2 + (size_t)s3 * NCLASS + sub * 4);
        acc.x += w0 * v0.x; acc.y += w0 * v0.y; acc.z += w0 * v0.z; acc.w += w0 * v0.w;
        acc.x += w1 * v1.x; acc.y += w1 * v1.y; acc.z += w1 * v1.z; acc.w += w1 * v1.w;
        acc.x += w2 * v2.x; acc.y += w2 * v2.y; acc.z += w2 * v2.z; acc.w += w2 * v2.w;
        acc.x += w3 * v3.x; acc.y += w3 * v3.y; acc.z += w3 * v3.z; acc.w += w3 * v3.w;
    }
    for (; e < end; e++) {
        int   s  = __ldg(&g_esrc[e]);
        float wt = __ldg(&g_ew[e]);
        float4 v = *(const float4*)(g_sup2 + (size_t)s * NCLASS + sub * 4);
        acc.x += wt * v.x; acc.y += wt * v.y; acc.z += wt * v.z; acc.w += wt * v.w;
    }
    float4 bv = *(const float4*)(b2 + sub * 4);
    acc.x += bv.x; acc.y += bv.y; acc.z += bv.z; acc.w += bv.w;

    // log_softmax across the 4-lane group (16 classes total)
    float m = fmaxf(fmaxf(acc.x, acc.y), fmaxf(acc.z, acc.w));
    m = fmaxf(m, __shfl_xor_sync(0xffffffffu, m, 1, 4));
    m = fmaxf(m, __shfl_xor_sync(0xffffffffu, m, 2, 4));

    float s = expf(acc.x - m) + expf(acc.y - m) +
              expf(acc.z - m) + expf(acc.w - m);
    s += __shfl_xor_sync(0xffffffffu, s, 1, 4);
    s += __shfl_xor_sync(0xffffffffu, s, 2, 4);

    float lse = m + logf(s);
    acc.x -= lse; acc.y -= lse; acc.z -= lse; acc.w -= lse;
    *(float4*)(out + (size_t)row * NCLASS + sub * 4) = acc;
}

// ---------------------------------------------------------------------------
// Launch sequence (graph-capturable, default stream, no allocations)
// ---------------------------------------------------------------------------
extern "C" void kernel_launch(void* const* d_in, const int* in_sizes, int n_in,
                              void* d_out, int out_size) {
    const float* x        = (const float*)d_in[0];
    const float* W1       = (const float*)d_in[1];
    const float* b1       = (const float*)d_in[2];
    const float* W2       = (const float*)d_in[3];
    const float* b2       = (const float*)d_in[4];
    const int*   edge_src = (const int*)d_in[5];
    const int*   edge_dst = (const int*)d_in[6];
    const float* edge_w   = (const float*)d_in[7];
    float* out = (float*)d_out;

    // CSR build (int atomics only)
    zero_deg_kernel<<<(N_NODES + 255) / 256, 256>>>();
    hist_kernel<<<(N_EDGES + 255) / 256, 256>>>(edge_dst);
    scan_kernel<<<1, 1024>>>();
    scatter_kernel<<<(N_EDGES + 255) / 256, 256>>>(edge_src, edge_dst, edge_w);

    // Dense pipeline (no float atomics anywhere)
    gemm1_kernel<<<(N_NODES + 63) / 64, 256>>>(x, W1);
    {
        long long threads = (long long)N_NODES * 16;
        spmm1_csr_kernel<<<(int)((threads + 255) / 256), 256>>>(b1);
    }
    gemm2_kernel<<<(N_NODES + 255) / 256, 256>>>(W2);
    {
        long long threads = (long long)N_NODES * 4;
        spmm2_csr_kernel<<<(int)((threads + 255) / 256), 256>>>(b2, out);
    }
}

// round 8
// speedup vs baseline: 1.0449x; 1.0449x over previous
#include <cuda_runtime.h>
#include <math.h>

#define N_NODES 50000
#define N_EDGES 1600000
#define NFEAT 256
#define NHID 64
#define NCLASS 16

// ---------------------------------------------------------------------------
// Static scratch — no cudaMalloc allowed anywhere.
// ---------------------------------------------------------------------------
__device__ float g_sup1[N_NODES * NHID];    // x @ W1
__device__ float g_h[N_NODES * NHID];       // spmm1 result + b1
__device__ float g_sup2[N_NODES * NCLASS];  // relu(h) @ W2
__device__ int   g_deg[N_NODES];            // per-dst edge counts
__device__ int   g_rowptr[N_NODES];         // CSR row starts (pristine)
__device__ int   g_pos[N_NODES];            // CSR fill cursors (mutated)
__device__ int2  g_edge[N_EDGES];           // packed {src, bits(weight)} CSR order

// ---------------------------------------------------------------------------
// 0) zero the histogram
// ---------------------------------------------------------------------------
__global__ void zero_deg_kernel() {
    int i = blockIdx.x * blockDim.x + threadIdx.x;
    if (i < N_NODES) g_deg[i] = 0;
}

// ---------------------------------------------------------------------------
// 1) histogram of dst — 4 edges per thread for atomic-latency hiding.
// ---------------------------------------------------------------------------
__global__ void hist_kernel(const int* __restrict__ dst) {
    const int NT = N_EDGES / 4;
    int t = blockIdx.x * blockDim.x + threadIdx.x;
    if (t >= NT) return;
    int d0 = __ldg(&dst[t + 0 * NT]);
    int d1 = __ldg(&dst[t + 1 * NT]);
    int d2 = __ldg(&dst[t + 2 * NT]);
    int d3 = __ldg(&dst[t + 3 * NT]);
    atomicAdd(&g_deg[d0], 1);
    atomicAdd(&g_deg[d1], 1);
    atomicAdd(&g_deg[d2], 1);
    atomicAdd(&g_deg[d3], 1);
}

// ---------------------------------------------------------------------------
// 2) exclusive scan over g_deg -> g_rowptr, g_pos (1 block, shfl warp scan)
// ---------------------------------------------------------------------------
__global__ void __launch_bounds__(1024)
scan_kernel() {
    __shared__ int warpsum[32];
    __shared__ int warpoff[32];
    __shared__ int carry_s;
    int tid  = threadIdx.x;
    int lane = tid & 31;
    int wrp  = tid >> 5;
    if (tid == 0) carry_s = 0;
    __syncthreads();

    for (int base = 0; base < N_NODES; base += 1024) {
        int i = base + tid;
        int v = (i < N_NODES) ? g_deg[i] : 0;

        int incl = v;
#pragma unroll
        for (int off = 1; off < 32; off <<= 1) {
            int t = __shfl_up_sync(0xffffffffu, incl, off);
            if (lane >= off) incl += t;
        }
        if (lane == 31) warpsum[wrp] = incl;
        __syncthreads();

        if (wrp == 0) {
            int s = warpsum[lane];
            int si = s;
#pragma unroll
            for (int off = 1; off < 32; off <<= 1) {
                int t = __shfl_up_sync(0xffffffffu, si, off);
                if (lane >= off) si += t;
            }
            warpoff[lane] = si - s;
        }
        __syncthreads();

        if (i < N_NODES) {
            int r = carry_s + warpoff[wrp] + incl - v;
            g_rowptr[i] = r;
            g_pos[i]    = r;
        }
        __syncthreads();
        if (tid == 0) carry_s += warpoff[31] + warpsum[31];
        __syncthreads();
    }
}

// ---------------------------------------------------------------------------
// 3) scatter edges into CSR order — 4 edges/thread ILP, packed int2 payload
// ---------------------------------------------------------------------------
__global__ void scatter_kernel(const int* __restrict__ src,
                               const int* __restrict__ dst,
                               const float* __restrict__ w) {
    const int NT = N_EDGES / 4;
    int t = blockIdx.x * blockDim.x + threadIdx.x;
    if (t >= NT) return;

    int   d0 = __ldg(&dst[t + 0 * NT]);
    int   d1 = __ldg(&dst[t + 1 * NT]);
    int   d2 = __ldg(&dst[t + 2 * NT]);
    int   d3 = __ldg(&dst[t + 3 * NT]);
    int   s0 = __ldg(&src[t + 0 * NT]);
    int   s1 = __ldg(&src[t + 1 * NT]);
    int   s2 = __ldg(&src[t + 2 * NT]);
    int   s3 = __ldg(&src[t + 3 * NT]);
    float w0 = __ldg(&w[t + 0 * NT]);
    float w1 = __ldg(&w[t + 1 * NT]);
    float w2 = __ldg(&w[t + 2 * NT]);
    float w3 = __ldg(&w[t + 3 * NT]);

    int p0 = atomicAdd(&g_pos[d0], 1);
    int p1 = atomicAdd(&g_pos[d1], 1);
    int p2 = atomicAdd(&g_pos[d2], 1);
    int p3 = atomicAdd(&g_pos[d3], 1);

    g_edge[p0] = make_int2(s0, __float_as_int(w0));
    g_edge[p1] = make_int2(s1, __float_as_int(w1));
    g_edge[p2] = make_int2(s2, __float_as_int(w2));
    g_edge[p3] = make_int2(s3, __float_as_int(w3));
}

// ---------------------------------------------------------------------------
// GEMM1: sup1[50000,64] = x[50000,256] @ W1[256,64]
// 64x64 tile, 256 threads, 4x4 register blocking, BK=16,
// global->register prefetch pipelining to hide tile-load latency.
// ---------------------------------------------------------------------------
__global__ void __launch_bounds__(256)
gemm1_kernel(const float* __restrict__ x, const float* __restrict__ W1) {
    __shared__ float xs[16][68];  // [kk][row], padded
    __shared__ float ws[16][64];  // [kk][col]

    int tid = threadIdx.x;
    int tx = tid & 15;
    int ty = tid >> 4;
    int rowBase = blockIdx.x * 64;

    int xr  = tid >> 2;             // 0..63 row within tile
    int xkq = (tid & 3) * 4;        // 0,4,8,12 k-quad
    int wkk = tid >> 4;             // 0..15 k within tile
    int wn  = (tid & 15) * 4;       // 0..60 col quad
    int grow = rowBase + xr;
    bool rowOK = (grow < N_NODES);

    float acc[4][4];
#pragma unroll
    for (int i = 0; i < 4; i++)
#pragma unroll
        for (int j = 0; j < 4; j++) acc[i][j] = 0.f;

    float4 xv = rowOK ? *(const float4*)(x + (size_t)grow * NFEAT + 0 + xkq)
                      : make_float4(0.f, 0.f, 0.f, 0.f);
    float4 wv = *(const float4*)(W1 + (size_t)(0 + wkk) * NHID + wn);

    for (int k0 = 0; k0 < NFEAT; k0 += 16) {
        xs[xkq + 0][xr] = xv.x;
        xs[xkq + 1][xr] = xv.y;
        xs[xkq + 2][xr] = xv.z;
        xs[xkq + 3][xr] = xv.w;
        *(float4*)&ws[wkk][wn] = wv;
        __syncthreads();

        int k1 = k0 + 16;
        if (k1 < NFEAT) {
            xv = rowOK ? *(const float4*)(x + (size_t)grow * NFEAT + k1 + xkq)
                       : make_float4(0.f, 0.f, 0.f, 0.f);
            wv = *(const float4*)(W1 + (size_t)(k1 + wkk) * NHID + wn);
        }

#pragma unroll
        for (int kk = 0; kk < 16; kk++) {
            float a0 = xs[kk][ty * 4 + 0];
            float a1 = xs[kk][ty * 4 + 1];
            float a2 = xs[kk][ty * 4 + 2];
            float a3 = xs[kk][ty * 4 + 3];
            float4 bv = *(float4*)&ws[kk][tx * 4];
            acc[0][0] += a0 * bv.x; acc[0][1] += a0 * bv.y; acc[0][2] += a0 * bv.z; acc[0][3] += a0 * bv.w;
            acc[1][0] += a1 * bv.x; acc[1][1] += a1 * bv.y; acc[1][2] += a1 * bv.z; acc[1][3] += a1 * bv.w;
            acc[2][0] += a2 * bv.x; acc[2][1] += a2 * bv.y; acc[2][2] += a2 * bv.z; acc[2][3] += a2 * bv.w;
            acc[3][0] += a3 * bv.x; acc[3][1] += a3 * bv.y; acc[3][2] += a3 * bv.z; acc[3][3] += a3 * bv.w;
        }
        __syncthreads();
    }

#pragma unroll
    for (int i = 0; i < 4; i++) {
        int gr = rowBase + ty * 4 + i;
        if (gr < N_NODES) {
            float4 v = make_float4(acc[i][0], acc[i][1], acc[i][2], acc[i][3]);
            *(float4*)(g_sup1 + (size_t)gr * NHID + tx * 4) = v;
        }
    }
}

// ---------------------------------------------------------------------------
// 4) SpMM1 gather: h[row] = b1 + sum_e w_e * sup1[src_e]
//    16 threads per row, each owns a float4. 8-way unrolled, packed int2.
// ---------------------------------------------------------------------------
__global__ void __launch_bounds__(256)
spmm1_csr_kernel(const float* __restrict__ b1) {
    long long t = (long long)blockIdx.x * blockDim.x + threadIdx.x;
    int row = (int)(t >> 4);
    int sub = (int)(t & 15);
    if (row >= N_NODES) return;

    int start = g_rowptr[row];
    int end   = start + g_deg[row];

    float4 acc = make_float4(0.f, 0.f, 0.f, 0.f);
    int e = start;
    for (; e + 8 <= end; e += 8) {
        int2 p[8];
#pragma unroll
        for (int u = 0; u < 8; u++) p[u] = __ldg(&g_edge[e + u]);
        float4 v[8];
#pragma unroll
        for (int u = 0; u < 8; u++)
            v[u] = *(const float4*)(g_sup1 + (size_t)p[u].x * NHID + sub * 4);
#pragma unroll
        for (int u = 0; u < 8; u++) {
            float wt = __int_as_float(p[u].y);
            acc.x += wt * v[u].x; acc.y += wt * v[u].y;
            acc.z += wt * v[u].z; acc.w += wt * v[u].w;
        }
    }
    for (; e < end; e++) {
        int2 p = __ldg(&g_edge[e]);
        float wt = __int_as_float(p.y);
        float4 v = *(const float4*)(g_sup1 + (size_t)p.x * NHID + sub * 4);
        acc.x += wt * v.x; acc.y += wt * v.y; acc.z += wt * v.z; acc.w += wt * v.w;
    }
    float4 bv = *(const float4*)(b1 + sub * 4);
    acc.x += bv.x; acc.y += bv.y; acc.z += bv.z; acc.w += bv.w;
    *(float4*)(g_h + (size_t)row * NHID + sub * 4) = acc;
}

// ---------------------------------------------------------------------------
// GEMM2: sup2[50000,16] = relu(h)[50000,64] @ W2[64,16]; one thread per row
// ---------------------------------------------------------------------------
__global__ void __launch_bounds__(256)
gemm2_kernel(const float* __restrict__ W2) {
    __shared__ float w2s[NHID * NCLASS];
    for (int i = threadIdx.x; i < NHID * NCLASS; i += blockDim.x)
        w2s[i] = W2[i];
    __syncthreads();

    int n = blockIdx.x * blockDim.x + threadIdx.x;
    if (n >= N_NODES) return;

    float acc[NCLASS];
#pragma unroll
    for (int c = 0; c < NCLASS; c++) acc[c] = 0.f;

    const float4* hrow = (const float4*)(g_h + (size_t)n * NHID);
#pragma unroll
    for (int k4 = 0; k4 < NHID / 4; k4++) {
        float4 hv = hrow[k4];
        hv.x = fmaxf(hv.x, 0.f);
        hv.y = fmaxf(hv.y, 0.f);
        hv.z = fmaxf(hv.z, 0.f);
        hv.w = fmaxf(hv.w, 0.f);
        int k = k4 * 4;
#pragma unroll
        for (int c = 0; c < NCLASS; c++) {
            acc[c] += hv.x * w2s[(k + 0) * NCLASS + c];
            acc[c] += hv.y * w2s[(k + 1) * NCLASS + c];
            acc[c] += hv.z * w2s[(k + 2) * NCLASS + c];
            acc[c] += hv.w * w2s[(k + 3) * NCLASS + c];
        }
    }
    float4* o = (float4*)(g_sup2 + (size_t)n * NCLASS);
#pragma unroll
    for (int q = 0; q < 4; q++)
        o[q] = make_float4(acc[q * 4 + 0], acc[q * 4 + 1],
                           acc[q * 4 + 2], acc[q * 4 + 3]);
}

// ---------------------------------------------------------------------------
// 5) SpMM2 gather + bias + log_softmax, fused. 4 threads/row, 8-way unroll.
// ---------------------------------------------------------------------------
__global__ void __launch_bounds__(256)
spmm2_csr_kernel(const float* __restrict__ b2, float* __restrict__ out) {
    long long t = (long long)blockIdx.x * blockDim.x + threadIdx.x;
    int row = (int)(t >> 2);
    int sub = (int)(t & 3);
    if (row >= N_NODES) return;

    int start = g_rowptr[row];
    int end   = start + g_deg[row];

    float4 acc = make_float4(0.f, 0.f, 0.f, 0.f);
    int e = start;
    for (; e + 8 <= end; e += 8) {
        int2 p[8];
#pragma unroll
        for (int u = 0; u < 8; u++) p[u] = __ldg(&g_edge[e + u]);
        float4 v[8];
#pragma unroll
        for (int u = 0; u < 8; u++)
            v[u] = *(const float4*)(g_sup2 + (size_t)p[u].x * NCLASS + sub * 4);
#pragma unroll
        for (int u = 0; u < 8; u++) {
            float wt = __int_as_float(p[u].y);
            acc.x += wt * v[u].x; acc.y += wt * v[u].y;
            acc.z += wt * v[u].z; acc.w += wt * v[u].w;
        }
    }
    for (; e < end; e++) {
        int2 p = __ldg(&g_edge[e]);
        float wt = __int_as_float(p.y);
        float4 v = *(const float4*)(g_sup2 + (size_t)p.x * NCLASS + sub * 4);
        acc.x += wt * v.x; acc.y += wt * v.y; acc.z += wt * v.z; acc.w += wt * v.w;
    }
    float4 bv = *(const float4*)(b2 + sub * 4);
    acc.x += bv.x; acc.y += bv.y; acc.z += bv.z; acc.w += bv.w;

    // log_softmax across the 4-lane group (16 classes total)
    float m = fmaxf(fmaxf(acc.x, acc.y), fmaxf(acc.z, acc.w));
    m = fmaxf(m, __shfl_xor_sync(0xffffffffu, m, 1, 4));
    m = fmaxf(m, __shfl_xor_sync(0xffffffffu, m, 2, 4));

    float s = expf(acc.x - m) + expf(acc.y - m) +
              expf(acc.z - m) + expf(acc.w - m);
    s += __shfl_xor_sync(0xffffffffu, s, 1, 4);
    s += __shfl_xor_sync(0xffffffffu, s, 2, 4);

    float lse = m + logf(s);
    acc.x -= lse; acc.y -= lse; acc.z -= lse; acc.w -= lse;
    *(float4*)(out + (size_t)row * NCLASS + sub * 4) = acc;
}

// ---------------------------------------------------------------------------
// Launch sequence (graph-capturable, default stream, no allocations)
// ---------------------------------------------------------------------------
extern "C" void kernel_launch(void* const* d_in, const int* in_sizes, int n_in,
                              void* d_out, int out_size) {
    const float* x        = (const float*)d_in[0];
    const float* W1       = (const float*)d_in[1];
    const float* b1       = (const float*)d_in[2];
    const float* W2       = (const float*)d_in[3];
    const float* b2       = (const float*)d_in[4];
    const int*   edge_src = (const int*)d_in[5];
    const int*   edge_dst = (const int*)d_in[6];
    const float* edge_w   = (const float*)d_in[7];
    float* out = (float*)d_out;

    // CSR build (int atomics only)
    zero_deg_kernel<<<(N_NODES + 255) / 256, 256>>>();
    hist_kernel<<<(N_EDGES / 4 + 255) / 256, 256>>>(edge_dst);
    scan_kernel<<<1, 1024>>>();
    scatter_kernel<<<(N_EDGES / 4 + 255) / 256, 256>>>(edge_src, edge_dst, edge_w);

    // Dense pipeline (no float atomics anywhere)
    gemm1_kernel<<<(N_NODES + 63) / 64, 256>>>(x, W1);
    {
        long long threads = (long long)N_NODES * 16;
        spmm1_csr_kernel<<<(int)((threads + 255) / 256), 256>>>(b1);
    }
    gemm2_kernel<<<(N_NODES + 255) / 256, 256>>>(W2);
    {
        long long threads = (long long)N_NODES * 4;
        spmm2_csr_kernel<<<(int)((threads + 255) / 256), 256>>>(b2, out);
    }
}